// round 9
// baseline (speedup 1.0000x reference)
#include <cuda_runtime.h>
#include <cuda_bf16.h>
#include <cstddef>

// score(f) = 1 + tanh(f.W + b)/10 ; e[parent] = score(c0)*e[c0] + score(c1)*e[c1]
// Complete binary tree, level order, D=21, N = 2^21 - 1, F = 64.
// One persistent kernel; 16-child warp tiles; folding butterfly; energy prefetch.
// 4 blocks/SM (64-reg cap) -> 32 warps/SM -> 32KB outstanding loads/SM.

#define TANH_INV_SCALAR 0.1f
#define NB       592         // 4 blocks/SM on 148 SMs -> all resident
#define NTHREADS 256
#define NWARPS   (NB * (NTHREADS / 32))

__device__ unsigned g_count = 0;
__device__ volatile unsigned g_gen = 0;

__device__ __forceinline__ void grid_barrier()
{
    __syncthreads();
    if (threadIdx.x == 0) {
        __threadfence();
        unsigned g = g_gen;
        if (atomicAdd(&g_count, 1u) == NB - 1u) {
            g_count = 0;
            __threadfence();
            g_gen = g + 1u;
        } else {
            while (g_gen == g) { __nanosleep(32); }
            __threadfence();
        }
    }
    __syncthreads();
}

__device__ __forceinline__ float tanh_fast(float x)
{
    float y;
    asm("tanh.approx.f32 %0, %1;" : "=f"(y) : "f"(x));
    return y;
}

// One warp processes one 16-child tile.
//   col = lane & 15 (fixed W slice), h = lane >> 4 (sibling half)
//   After the fold, each lane holds the full dot of row r = 2*vi + h.
__device__ __forceinline__ void do_tile(
    const float* __restrict__ features,
    const float* __restrict__ leaf_energy,
    float* __restrict__ energy,
    float4 wv, float b,
    int cstart, int pstart, int tile, int lane, int r, int vi,
    bool leaf_level, int leaf_start)
{
    const int cbase = cstart + tile * 16;
    const bool s3 = lane & 8, s2 = lane & 4, s1 = lane & 2;
    const int  h  = lane >> 4;
    const int  ci = cbase + r;

    // Prefetch energy operand first (independent of the dot).
    float e;
    if (leaf_level) e = __ldg(&leaf_energy[ci - leaf_start]);
    else            e = __ldcg(&energy[ci]);

    // 8 independent coalesced float4 loads (4 KB tile).
    const float4* g = reinterpret_cast<const float4*>(features + (size_t)cbase * 64);
    float part[8];
    #pragma unroll
    for (int j = 0; j < 8; ++j) {
        float4 v = __ldg(&g[j * 32 + lane]);
        part[j] = v.x * wv.x + v.y * wv.y + v.z * wv.z + v.w * wv.w;
    }

    // Folding butterfly: 15 shuffles; every lane ends with one full row dot.
    float a4[4];
    #pragma unroll
    for (int j = 0; j < 4; ++j) {
        float u0 = part[2*j]   + __shfl_xor_sync(~0u, part[2*j],   8);
        float u1 = part[2*j+1] + __shfl_xor_sync(~0u, part[2*j+1], 8);
        a4[j] = s3 ? u1 : u0;
    }
    float a2[2];
    #pragma unroll
    for (int j = 0; j < 2; ++j) {
        float u0 = a4[2*j]   + __shfl_xor_sync(~0u, a4[2*j],   4);
        float u1 = a4[2*j+1] + __shfl_xor_sync(~0u, a4[2*j+1], 4);
        a2[j] = s2 ? u1 : u0;
    }
    float u0 = a2[0] + __shfl_xor_sync(~0u, a2[0], 2);
    float u1 = a2[1] + __shfl_xor_sync(~0u, a2[1], 2);
    float a1 = s1 ? u1 : u0;
    float dot = a1 + __shfl_xor_sync(~0u, a1, 1);

    if (leaf_level && (lane & 1) == 0)
        __stcg(&energy[ci], e);                  // seed output leaves inline

    float s = 1.0f + tanh_fast(dot + b) * TANH_INV_SCALAR;
    float contrib = s * e;
    float other = __shfl_xor_sync(~0u, contrib, 16);   // sibling half
    if (h == 0 && (lane & 1) == 0)
        __stcg(&energy[pstart + tile * 8 + vi], contrib + other);
}

__global__ void __launch_bounds__(NTHREADS, 4)
tree_all_kernel(const float* __restrict__ features,
                const float* __restrict__ leaf_energy,
                const float* __restrict__ W,
                const float* __restrict__ bptr,
                float* __restrict__ energy)
{
    const int tid   = threadIdx.x;
    const int lane  = tid & 31;
    const int gwarp = (blockIdx.x * NTHREADS + tid) >> 5;

    const float4 wv = reinterpret_cast<const float4*>(W)[lane & 15];
    const float  b  = __ldg(bptr);

    const int h  = lane >> 4;
    const int vi = ((lane >> 3) & 1) | (((lane >> 2) & 1) << 1)
                 | (((lane >> 1) & 1) << 2);
    const int r  = 2 * vi + h;

    const int NLEAF = 1 << 20;
    const int leaf_start = NLEAF - 1;

    // ---- Grid-wide levels d = 20 .. 12 ----
    for (int d = 20; d >= 12; --d) {
        const int nc     = 1 << d;
        const int cstart = nc - 1;
        const int pstart = (nc >> 1) - 1;
        const int ntiles = nc >> 4;
        const bool leaf_level = (d == 20);

        for (int tile = gwarp; tile < ntiles; tile += NWARPS)
            do_tile(features, leaf_energy, energy, wv, b,
                    cstart, pstart, tile, lane, r, vi, leaf_level, leaf_start);
        grid_barrier();
    }

    // ---- Single-block tail: levels d = 11 .. 1 ----
    if (blockIdx.x != 0) return;
    const int bwarp = tid >> 5;

    for (int d = 11; d >= 5; --d) {
        const int nc     = 1 << d;
        const int cstart = nc - 1;
        const int pstart = (nc >> 1) - 1;
        const int ntiles = nc >> 4;
        for (int tile = bwarp; tile < ntiles; tile += NTHREADS / 32)
            do_tile(features, leaf_energy, energy, wv, b,
                    cstart, pstart, tile, lane, r, vi, false, leaf_start);
        __syncthreads();
    }

    for (int d = 4; d >= 1; --d) {
        const int nc     = 1 << d;
        const int cstart = nc - 1;
        const int pstart = (nc >> 1) - 1;
        if (tid < 32) {
            float contrib = 0.0f;
            if (lane < nc) {
                const int ch = cstart + lane;
                const float* f = features + (size_t)ch * 64;
                float dot = 0.0f;
                #pragma unroll
                for (int k = 0; k < 64; ++k)
                    dot += __ldg(&f[k]) * __ldg(&W[k]);
                float s = 1.0f + tanh_fast(dot + b) * TANH_INV_SCALAR;
                contrib = s * __ldcg(&energy[ch]);
            }
            float other = __shfl_xor_sync(~0u, contrib, 1);
            if (lane < nc && (lane & 1) == 0)
                __stcg(&energy[pstart + (lane >> 1)], contrib + other);
        }
        __syncthreads();
    }
}

extern "C" void kernel_launch(void* const* d_in, const int* in_sizes, int n_in,
                              void* d_out, int out_size)
{
    const float* features    = (const float*)d_in[0];   // [N, 64]
    const float* leaf_energy = (const float*)d_in[1];   // [2^20]
    const float* W           = (const float*)d_in[2];   // [64]
    const float* bptr        = (const float*)d_in[3];   // [1]
    float* energy = (float*)d_out;                      // [N]

    tree_all_kernel<<<NB, NTHREADS>>>(features, leaf_energy, W, bptr, energy);
}